// round 1
// baseline (speedup 1.0000x reference)
#include <cuda_runtime.h>
#include <cuda_bf16.h>
#include <math.h>

// Problem constants (fixed by the dataset)
constexpr int N_NODES = 50000;
constexpr int E_EDGES = 800000;
constexpr int DIN     = 128;      // also H*D_HEAD
constexpr int NHEAD   = 8;
constexpr int DHEAD   = 16;
constexpr float INV_SCALE = 0.25f;   // 1/sqrt(16)

// Scratch (device globals — no allocation allowed)
__device__ float g_Q[N_NODES * DIN];
__device__ float g_K[N_NODES * DIN];
__device__ float g_V[N_NODES * DIN];
__device__ float g_z[N_NODES * NHEAD];

// ---------------------------------------------------------------------------
// Kernel 1: zero the accumulators (d_out is poisoned by the harness)
// ---------------------------------------------------------------------------
__global__ void zero_kernel(float* __restrict__ out)
{
    const int stride = gridDim.x * blockDim.x;
    int i = blockIdx.x * blockDim.x + threadIdx.x;
    float4 zv = make_float4(0.f, 0.f, 0.f, 0.f);
    float4* o4 = reinterpret_cast<float4*>(out);
    float4* z4 = reinterpret_cast<float4*>(g_z);
    constexpr int NOUT4 = N_NODES * DIN / 4;
    constexpr int NZ4   = N_NODES * NHEAD / 4;
    for (int j = i; j < NOUT4; j += stride) o4[j] = zv;
    for (int j = i; j < NZ4;   j += stride) z4[j] = zv;
}

// ---------------------------------------------------------------------------
// Kernel 2: fused QKV GEMM.  C[50000 x 384] = h[50000 x 128] @ {Wq|Wk|Wv}
// blockIdx.y in [0,6): tiles 0-1 -> Q, 2-3 -> K, 4-5 -> V (64 cols each).
// BM=64, BN=64, BK=32, 256 threads, 4x4 register tile per thread.
// ---------------------------------------------------------------------------
constexpr int BM = 64, BN = 64, BK = 32;

__global__ __launch_bounds__(256)
void qkv_gemm_kernel(const float* __restrict__ h,
                     const float* __restrict__ Wq, const float* __restrict__ bq,
                     const float* __restrict__ Wk, const float* __restrict__ bk,
                     const float* __restrict__ Wv, const float* __restrict__ bv)
{
    __shared__ float sA[BK][BM];   // transposed h tile
    __shared__ float sB[BK][BN];   // W tile

    const int tid  = threadIdx.x;
    const int row0 = blockIdx.x * BM;
    const int by   = blockIdx.y;

    const float* W    = (by < 2) ? Wq : (by < 4 ? Wk : Wv);
    const float* bias = (by < 2) ? bq : (by < 4 ? bk : bv);
    float*       outp = (by < 2) ? g_Q : (by < 4 ? g_K : g_V);
    const int c0 = (by & 1) * 64;    // column offset within the 128-wide matrix

    const int tr = tid >> 4;   // 0..15
    const int tc = tid & 15;   // 0..15

    float acc[4][4];
#pragma unroll
    for (int i = 0; i < 4; i++)
#pragma unroll
        for (int j = 0; j < 4; j++) acc[i][j] = 0.f;

    for (int k0 = 0; k0 < DIN; k0 += BK) {
        // load A tile: 64 rows x 32 k, 2 float4 per thread, store transposed
#pragma unroll
        for (int p = 0; p < 2; p++) {
            int r  = p * 32 + (tid >> 3);       // 0..63
            int k4 = (tid & 7) * 4;             // 0..28
            int gr = row0 + r;
            int src = (gr < N_NODES ? gr : N_NODES - 1) * DIN + k0 + k4;
            float4 v = *reinterpret_cast<const float4*>(&h[src]);
            sA[k4 + 0][r] = v.x;
            sA[k4 + 1][r] = v.y;
            sA[k4 + 2][r] = v.z;
            sA[k4 + 3][r] = v.w;
        }
        // load B tile: 32 k x 64 cols, 2 float4 per thread
#pragma unroll
        for (int p = 0; p < 2; p++) {
            int k  = p * 16 + (tid >> 4);       // 0..31
            int c4 = (tid & 15) * 4;            // 0..60
            float4 v = *reinterpret_cast<const float4*>(&W[(k0 + k) * DIN + c0 + c4]);
            *reinterpret_cast<float4*>(&sB[k][c4]) = v;
        }
        __syncthreads();

#pragma unroll
        for (int k = 0; k < BK; k++) {
            float4 a = *reinterpret_cast<const float4*>(&sA[k][tr * 4]);
            float4 b = *reinterpret_cast<const float4*>(&sB[k][tc * 4]);
            float av[4] = {a.x, a.y, a.z, a.w};
            float bv4[4] = {b.x, b.y, b.z, b.w};
#pragma unroll
            for (int i = 0; i < 4; i++)
#pragma unroll
                for (int j = 0; j < 4; j++) acc[i][j] += av[i] * bv4[j];
        }
        __syncthreads();
    }

    // epilogue: bias + store
    float4 bvv = *reinterpret_cast<const float4*>(&bias[c0 + tc * 4]);
    float bb[4] = {bvv.x, bvv.y, bvv.z, bvv.w};
#pragma unroll
    for (int i = 0; i < 4; i++) {
        int gr = row0 + tr * 4 + i;
        if (gr < N_NODES) {
            float4 o;
            o.x = acc[i][0] + bb[0];
            o.y = acc[i][1] + bb[1];
            o.z = acc[i][2] + bb[2];
            o.w = acc[i][3] + bb[3];
            *reinterpret_cast<float4*>(&outp[gr * DIN + c0 + tc * 4]) = o;
        }
    }
}

// ---------------------------------------------------------------------------
// Kernel 3: edge scatter. One warp per edge.
// lane l handles floats [4l, 4l+4) of the 128-float row; head = l/4.
// ---------------------------------------------------------------------------
__global__ __launch_bounds__(256)
void edge_kernel(const int* __restrict__ src, const int* __restrict__ dst,
                 float* __restrict__ wV)
{
    const int warp = (blockIdx.x * blockDim.x + threadIdx.x) >> 5;
    const int lane = threadIdx.x & 31;
    if (warp >= E_EDGES) return;

    const int s = src[warp];
    const int d = dst[warp];

    const float4 kv = *reinterpret_cast<const float4*>(&g_K[s * DIN + lane * 4]);
    const float4 qv = *reinterpret_cast<const float4*>(&g_Q[d * DIN + lane * 4]);

    float part = kv.x * qv.x + kv.y * qv.y + kv.z * qv.z + kv.w * qv.w;
    // reduce over the 4 lanes of this head
    part += __shfl_xor_sync(0xFFFFFFFFu, part, 1);
    part += __shfl_xor_sync(0xFFFFFFFFu, part, 2);

    float x = part * INV_SCALE;
    x = fminf(fmaxf(x, -5.0f), 5.0f);
    const float sc = __expf(x);

    const float4 vv = *reinterpret_cast<const float4*>(&g_V[s * DIN + lane * 4]);
    float* addr = wV + d * DIN + lane * 4;
    asm volatile("red.global.add.v4.f32 [%0], {%1, %2, %3, %4};"
                 :: "l"(addr),
                    "f"(vv.x * sc), "f"(vv.y * sc), "f"(vv.z * sc), "f"(vv.w * sc)
                 : "memory");

    if ((lane & 3) == 0)
        atomicAdd(&g_z[d * NHEAD + (lane >> 2)], sc);
}

// ---------------------------------------------------------------------------
// Kernel 4: normalize in place: out[i] /= (z[i/16] + 1e-6)
// ---------------------------------------------------------------------------
__global__ void normalize_kernel(float* __restrict__ out)
{
    const int i4 = (blockIdx.x * blockDim.x + threadIdx.x) * 4;
    if (i4 >= N_NODES * DIN) return;
    const float zr = 1.0f / (g_z[i4 >> 4] + 1e-6f);
    float4 v = *reinterpret_cast<float4*>(&out[i4]);
    v.x *= zr; v.y *= zr; v.z *= zr; v.w *= zr;
    *reinterpret_cast<float4*>(&out[i4]) = v;
}

// ---------------------------------------------------------------------------
extern "C" void kernel_launch(void* const* d_in, const int* in_sizes, int n_in,
                              void* d_out, int out_size)
{
    const float* h  = (const float*)d_in[0];
    const float* Wq = (const float*)d_in[1];
    const float* bq = (const float*)d_in[2];
    const float* Wk = (const float*)d_in[3];
    const float* bk = (const float*)d_in[4];
    const float* Wv = (const float*)d_in[5];
    const float* bv = (const float*)d_in[6];
    const int*   src = (const int*)d_in[7];
    const int*   dst = (const int*)d_in[8];
    float* out = (float*)d_out;

    // 1. zero accumulators
    zero_kernel<<<2048, 256>>>(out);

    // 2. fused QKV projection
    dim3 ggrid((N_NODES + BM - 1) / BM, 6);
    qkv_gemm_kernel<<<ggrid, 256>>>(h, Wq, bq, Wk, bk, Wv, bv);

    // 3. edge scatter: one warp per edge, 8 edges per 256-thread block
    const int eblocks = (E_EDGES + 7) / 8;
    edge_kernel<<<eblocks, 256>>>(src, dst, out);

    // 4. normalize
    const int nthreads4 = N_NODES * DIN / 4;
    normalize_kernel<<<(nthreads4 + 255) / 256, 256>>>(out);
}

// round 3
// speedup vs baseline: 1.1077x; 1.1077x over previous
#include <cuda_runtime.h>
#include <cuda_fp16.h>
#include <math.h>

// Problem constants (fixed by the dataset)
constexpr int N_NODES = 50000;
constexpr int E_EDGES = 800000;
constexpr int DIN     = 128;      // also H*D_HEAD
constexpr int NHEAD   = 8;
constexpr float INV_SCALE = 0.25f;   // 1/sqrt(16)

// Scratch (device globals — no allocation allowed). Q/K/V stored as fp16
// to halve L2 traffic in the edge phase (precision budget allows it).
__device__ __half g_Qh[N_NODES * DIN];
__device__ __half g_Kh[N_NODES * DIN];
__device__ __half g_Vh[N_NODES * DIN];
__device__ float  g_z[N_NODES * NHEAD];

// ---------------------------------------------------------------------------
// Kernel 1: zero the accumulators (d_out is poisoned by the harness)
// ---------------------------------------------------------------------------
__global__ void zero_kernel(float* __restrict__ out)
{
    const int stride = gridDim.x * blockDim.x;
    int i = blockIdx.x * blockDim.x + threadIdx.x;
    float4 zv = make_float4(0.f, 0.f, 0.f, 0.f);
    float4* o4 = reinterpret_cast<float4*>(out);
    float4* z4 = reinterpret_cast<float4*>(g_z);
    constexpr int NOUT4 = N_NODES * DIN / 4;
    constexpr int NZ4   = N_NODES * NHEAD / 4;
    for (int j = i; j < NOUT4; j += stride) o4[j] = zv;
    for (int j = i; j < NZ4;   j += stride) z4[j] = zv;
}

// ---------------------------------------------------------------------------
// Kernel 2: fused QKV GEMM.  C[50000 x 384] = h[50000 x 128] @ {Wq|Wk|Wv}
// blockIdx.y in [0,6): tiles 0-1 -> Q, 2-3 -> K, 4-5 -> V (64 cols each).
// BM=64, BN=64, BK=32, 256 threads, 4x4 register tile per thread.
// fp32 math, fp16 stores.
// ---------------------------------------------------------------------------
constexpr int BM = 64, BN = 64, BK = 32;

__global__ __launch_bounds__(256)
void qkv_gemm_kernel(const float* __restrict__ h,
                     const float* __restrict__ Wq, const float* __restrict__ bq,
                     const float* __restrict__ Wk, const float* __restrict__ bk,
                     const float* __restrict__ Wv, const float* __restrict__ bv)
{
    __shared__ float sA[BK][BM];   // transposed h tile
    __shared__ float sB[BK][BN];   // W tile

    const int tid  = threadIdx.x;
    const int row0 = blockIdx.x * BM;
    const int by   = blockIdx.y;

    const float* W    = (by < 2) ? Wq : (by < 4 ? Wk : Wv);
    const float* bias = (by < 2) ? bq : (by < 4 ? bk : bv);
    __half*      outp = (by < 2) ? g_Qh : (by < 4 ? g_Kh : g_Vh);
    const int c0 = (by & 1) * 64;    // column offset within the 128-wide matrix

    const int tr = tid >> 4;   // 0..15
    const int tc = tid & 15;   // 0..15

    float acc[4][4];
#pragma unroll
    for (int i = 0; i < 4; i++)
#pragma unroll
        for (int j = 0; j < 4; j++) acc[i][j] = 0.f;

    for (int k0 = 0; k0 < DIN; k0 += BK) {
        // load A tile: 64 rows x 32 k, 2 float4 per thread, store transposed
#pragma unroll
        for (int p = 0; p < 2; p++) {
            int r  = p * 32 + (tid >> 3);       // 0..63
            int k4 = (tid & 7) * 4;             // 0..28
            int gr = row0 + r;
            int src = (gr < N_NODES ? gr : N_NODES - 1) * DIN + k0 + k4;
            float4 v = *reinterpret_cast<const float4*>(&h[src]);
            sA[k4 + 0][r] = v.x;
            sA[k4 + 1][r] = v.y;
            sA[k4 + 2][r] = v.z;
            sA[k4 + 3][r] = v.w;
        }
        // load B tile: 32 k x 64 cols, 2 float4 per thread
#pragma unroll
        for (int p = 0; p < 2; p++) {
            int k  = p * 16 + (tid >> 4);       // 0..31
            int c4 = (tid & 15) * 4;            // 0..60
            float4 v = *reinterpret_cast<const float4*>(&W[(k0 + k) * DIN + c0 + c4]);
            *reinterpret_cast<float4*>(&sB[k][c4]) = v;
        }
        __syncthreads();

#pragma unroll
        for (int k = 0; k < BK; k++) {
            float4 a = *reinterpret_cast<const float4*>(&sA[k][tr * 4]);
            float4 b = *reinterpret_cast<const float4*>(&sB[k][tc * 4]);
            float av[4] = {a.x, a.y, a.z, a.w};
            float bv4[4] = {b.x, b.y, b.z, b.w};
#pragma unroll
            for (int i = 0; i < 4; i++)
#pragma unroll
                for (int j = 0; j < 4; j++) acc[i][j] += av[i] * bv4[j];
        }
        __syncthreads();
    }

    // epilogue: bias + convert to fp16 + store (8 bytes per row-chunk)
    float4 bvv = *reinterpret_cast<const float4*>(&bias[c0 + tc * 4]);
    float bb[4] = {bvv.x, bvv.y, bvv.z, bvv.w};
#pragma unroll
    for (int i = 0; i < 4; i++) {
        int gr = row0 + tr * 4 + i;
        if (gr < N_NODES) {
            __half2 lo = __floats2half2_rn(acc[i][0] + bb[0], acc[i][1] + bb[1]);
            __half2 hi = __floats2half2_rn(acc[i][2] + bb[2], acc[i][3] + bb[3]);
            uint2 packed;
            packed.x = *reinterpret_cast<unsigned*>(&lo);
            packed.y = *reinterpret_cast<unsigned*>(&hi);
            *reinterpret_cast<uint2*>(&outp[gr * DIN + c0 + tc * 4]) = packed;
        }
    }
}

// ---------------------------------------------------------------------------
// Kernel 3: edge scatter. One warp per edge.
// lane l handles elements [4l, 4l+4) of the 128-elem row; head = l>>2.
// fp16 loads (8B per lane per row), fp32 math + fp32 vector red.
// ---------------------------------------------------------------------------
__global__ __launch_bounds__(256)
void edge_kernel(const int* __restrict__ src, const int* __restrict__ dst,
                 float* __restrict__ wV)
{
    const int warp = (blockIdx.x * blockDim.x + threadIdx.x) >> 5;
    const int lane = threadIdx.x & 31;
    if (warp >= E_EDGES) return;

    const int s = src[warp];
    const int d = dst[warp];

    const uint2 kraw = *reinterpret_cast<const uint2*>(&g_Kh[s * DIN + lane * 4]);
    const uint2 qraw = *reinterpret_cast<const uint2*>(&g_Qh[d * DIN + lane * 4]);
    const uint2 vraw = *reinterpret_cast<const uint2*>(&g_Vh[s * DIN + lane * 4]);

    const float2 k0 = __half22float2(*reinterpret_cast<const __half2*>(&kraw.x));
    const float2 k1 = __half22float2(*reinterpret_cast<const __half2*>(&kraw.y));
    const float2 q0 = __half22float2(*reinterpret_cast<const __half2*>(&qraw.x));
    const float2 q1 = __half22float2(*reinterpret_cast<const __half2*>(&qraw.y));

    float part = k0.x * q0.x + k0.y * q0.y + k1.x * q1.x + k1.y * q1.y;
    // reduce over the 4 lanes of this head
    part += __shfl_xor_sync(0xFFFFFFFFu, part, 1);
    part += __shfl_xor_sync(0xFFFFFFFFu, part, 2);

    float x = part * INV_SCALE;
    x = fminf(fmaxf(x, -5.0f), 5.0f);
    const float sc = __expf(x);

    const float2 v0 = __half22float2(*reinterpret_cast<const __half2*>(&vraw.x));
    const float2 v1 = __half22float2(*reinterpret_cast<const __half2*>(&vraw.y));

    float* addr = wV + d * DIN + lane * 4;
    asm volatile("red.global.add.v4.f32 [%0], {%1, %2, %3, %4};"
                 :: "l"(addr),
                    "f"(v0.x * sc), "f"(v0.y * sc), "f"(v1.x * sc), "f"(v1.y * sc)
                 : "memory");

    if ((lane & 3) == 0)
        atomicAdd(&g_z[d * NHEAD + (lane >> 2)], sc);
}

// ---------------------------------------------------------------------------
// Kernel 4: normalize in place: out[i] /= (z[i/16] + 1e-6)
// ---------------------------------------------------------------------------
__global__ void normalize_kernel(float* __restrict__ out)
{
    const int i4 = (blockIdx.x * blockDim.x + threadIdx.x) * 4;
    if (i4 >= N_NODES * DIN) return;
    const float zr = 1.0f / (g_z[i4 >> 4] + 1e-6f);
    float4 v = *reinterpret_cast<float4*>(&out[i4]);
    v.x *= zr; v.y *= zr; v.z *= zr; v.w *= zr;
    *reinterpret_cast<float4*>(&out[i4]) = v;
}

// ---------------------------------------------------------------------------
extern "C" void kernel_launch(void* const* d_in, const int* in_sizes, int n_in,
                              void* d_out, int out_size)
{
    const float* h  = (const float*)d_in[0];
    const float* Wq = (const float*)d_in[1];
    const float* bq = (const float*)d_in[2];
    const float* Wk = (const float*)d_in[3];
    const float* bk = (const float*)d_in[4];
    const float* Wv = (const float*)d_in[5];
    const float* bv = (const float*)d_in[6];
    const int*   src = (const int*)d_in[7];
    const int*   dst = (const int*)d_in[8];
    float* out = (float*)d_out;

    // 1. zero accumulators
    zero_kernel<<<2048, 256>>>(out);

    // 2. fused QKV projection (fp32 math, fp16 stores)
    dim3 ggrid((N_NODES + BM - 1) / BM, 6);
    qkv_gemm_kernel<<<ggrid, 256>>>(h, Wq, bq, Wk, bk, Wv, bv);

    // 3. edge scatter: one warp per edge, 8 edges per 256-thread block
    const int eblocks = (E_EDGES + 7) / 8;
    edge_kernel<<<eblocks, 256>>>(src, dst, out);

    // 4. normalize
    const int nthreads4 = N_NODES * DIN / 4;
    normalize_kernel<<<(nthreads4 + 255) / 256, 256>>>(out);
}